// round 9
// baseline (speedup 1.0000x reference)
#include <cuda_runtime.h>
#include <cstdint>

#define CHAR_EMB 30
#define NFILT    30
#define MAXW     40
#define NCHARS   102
#define TH       128          // 4 warps/block, one position per warp

typedef unsigned long long ull;

__device__ __forceinline__ ull pk2(float lo, float hi) {
    ull r;
    asm("mov.b64 %0, {%1, %2};" : "=l"(r) : "f"(lo), "f"(hi));
    return r;
}
__device__ __forceinline__ void upk2(float& lo, float& hi, ull v) {
    asm("mov.b64 {%0, %1}, %2;" : "=f"(lo), "=f"(hi) : "l"(v));
}
__device__ __forceinline__ ull fma2(ull a, ull b, ull c) {
    ull d;
    asm("fma.rn.f32x2 %0, %1, %2, %3;" : "=l"(d) : "l"(a), "l"(b), "l"(c));
    return d;
}
__device__ __forceinline__ ull mul2(ull a, ull b) {
    ull d;
    asm("mul.rn.f32x2 %0, %1, %2;" : "=l"(d) : "l"(a), "l"(b));
    return d;
}

// Persistent warp-autonomous encoder, two time-passes (halved x registers ->
// 6 blocks/SM). Tables loaded once per block; no barriers after init.
// Pass A: y[0..19] -> raw max to out. Pass B: y[18..37] -> merge + bias.
__global__ __launch_bounds__(TH, 6)
void encoder_kernel(const int*    __restrict__ char_ids,
                    const int*    __restrict__ word_ids,
                    const float*  __restrict__ char_emb,
                    const float*  __restrict__ conv_w,
                    const float*  __restrict__ conv_b,
                    const float4* __restrict__ glove4,
                    float*        __restrict__ out,
                    int n_pos)
{
    __shared__ float      emb_s[NCHARS * 32];   // [char][e], padded row 32
    __shared__ ulonglong2 wsA[900];             // [f*30+e] = {w0pair, w1pair}
    __shared__ float2     wsC[900];             // [f*30+e] = {w2, bias}

    const int tid  = threadIdx.x;
    const int lane = tid & 31;
    const int wrp  = tid >> 5;

    for (int i = tid; i < NCHARS * CHAR_EMB; i += TH)
        emb_s[(i / CHAR_EMB) * 32 + (i % CHAR_EMB)] = char_emb[i];
    for (int oc = tid; oc < 900; oc += TH) {
        const int e = oc / NFILT, f = oc % NFILT;
        const float* wp = conv_w + (size_t)oc * 3;
        ulonglong2 a;
        a.x = pk2(wp[0], wp[0]);
        a.y = pk2(wp[1], wp[1]);
        wsA[f * 30 + e] = a;
        wsC[f * 30 + e] = make_float2(wp[2], conv_b[oc]);
    }
    __syncthreads();

    const int el = (lane < CHAR_EMB) ? lane : CHAR_EMB - 1;  // safe emb column
    const int wstride = gridDim.x * (TH / 32);
    int p = blockIdx.x * (TH / 32) + wrp;
    if (p >= n_pos) return;

    int2 c = make_int2(0, 0);
    if (lane < 20) c = reinterpret_cast<const int2*>(char_ids)[(size_t)p * 20 + lane];

    while (true) {
        const int pn = p + wstride;
        int2 cn = make_int2(0, 0);
        if (pn < n_pos && lane < 20)
            cn = reinterpret_cast<const int2*>(char_ids)[(size_t)pn * 20 + lane];

        // glove gather (independent memory work, overlaps compute)
        if (lane < 25) {
            const int wid = word_ids[p];
            reinterpret_cast<float4*>(out)[(size_t)p * 250 + 225 + lane] =
                glove4[(size_t)wid * 25 + lane];
        }

        float* outp = out + (size_t)p * 1000 + el * NFILT;

#define EV(t) emb_s[__shfl_sync(0xFFFFFFFFu, (((t) & 1) ? c.y : c.x), (t) >> 1) * 32 + el]

        // ============ PASS A: y[0..19] from x[0..21] ============
        {
            ull xe[11], xo[10];
            float x0 = EV(0);
            float x1 = EV(1);
            xe[0] = pk2(x0, x1);
#pragma unroll
            for (int i = 1; i < 11; i++) {
                float x2 = EV(2 * i);
                float x3 = EV(2 * i + 1);
                xe[i]     = pk2(x2, x3);
                xo[i - 1] = pk2(x1, x2);
                x1 = x3;
            }
            if (lane < CHAR_EMB) {
#pragma unroll 3
                for (int f = 0; f < NFILT; f++) {
                    const ulonglong2 wa = wsA[f * 30 + lane];
                    const float2     wc = wsC[f * 30 + lane];
                    const ull w2p = pk2(wc.x, wc.x);
                    float m0 = -3.402823466e+38f, m1 = m0;
#pragma unroll
                    for (int i = 0; i < 10; i++) {
                        ull acc = mul2(w2p, xe[i + 1]);
                        acc = fma2(wa.y, xo[i], acc);
                        acc = fma2(wa.x, xe[i], acc);
                        float lo, hi;
                        upk2(lo, hi, acc);
                        m0 = fmaxf(m0, lo);
                        m1 = fmaxf(m1, hi);
                    }
                    outp[f] = fmaxf(m0, m1);     // raw partial max
                }
            }
        }

        // ============ PASS B: y[18..37] from x[18..39] ============
        {
            ull xe[11], xo[10];
            float x0 = EV(18);
            float x1 = EV(19);
            xe[0] = pk2(x0, x1);
#pragma unroll
            for (int i = 1; i < 11; i++) {
                float x2 = EV(18 + 2 * i);
                float x3 = EV(19 + 2 * i);
                xe[i]     = pk2(x2, x3);
                xo[i - 1] = pk2(x1, x2);
                x1 = x3;
            }
            if (lane < CHAR_EMB) {
#pragma unroll 3
                for (int f = 0; f < NFILT; f++) {
                    const ulonglong2 wa = wsA[f * 30 + lane];
                    const float2     wc = wsC[f * 30 + lane];
                    const ull w2p = pk2(wc.x, wc.x);
                    float m0 = -3.402823466e+38f, m1 = m0;
#pragma unroll
                    for (int i = 0; i < 10; i++) {
                        ull acc = mul2(w2p, xe[i + 1]);
                        acc = fma2(wa.y, xo[i], acc);
                        acc = fma2(wa.x, xe[i], acc);
                        float lo, hi;
                        upk2(lo, hi, acc);
                        m0 = fmaxf(m0, lo);
                        m1 = fmaxf(m1, hi);
                    }
                    const float prev = outp[f];  // pass-A partial (L1 hit)
                    outp[f] = fmaxf(prev, fmaxf(m0, m1)) + wc.y;
                }
            }
        }
#undef EV

        if (pn >= n_pos) break;
        p = pn;
        c = cn;
    }
}

extern "C" void kernel_launch(void* const* d_in, const int* in_sizes, int n_in,
                              void* d_out, int out_size)
{
    const int*   char_ids = (const int*)d_in[0];
    const int*   word_ids = (const int*)d_in[1];
    const float* char_emb = (const float*)d_in[2];
    const float* conv_w   = (const float*)d_in[3];
    const float* conv_b   = (const float*)d_in[4];
    const float* glove    = (const float*)d_in[5];
    float*       out      = (float*)d_out;

    const int n_pos = in_sizes[1];   // B*S

    int blocks = 888;                // 6 resident blocks/SM on 148 SMs
    if (blocks * (TH / 32) > n_pos) blocks = (n_pos + TH / 32 - 1) / (TH / 32);
    encoder_kernel<<<blocks, TH>>>(char_ids, word_ids, char_emb, conv_w, conv_b,
                                   (const float4*)glove, out, n_pos);
}

// round 10
// speedup vs baseline: 1.5767x; 1.5767x over previous
#include <cuda_runtime.h>
#include <cstdint>

#define CHAR_EMB 30
#define NFILT    30
#define MAXW     40
#define NCHARS   102
#define TH       128          // 4 warps/block, one position per warp

typedef unsigned long long ull;

// ---------- packed f32x2 helpers: unions so ptxas can alias pairs ----------
union F2U { float2 f; ull u; };

__device__ __forceinline__ ull pk2(float lo, float hi) {
    F2U v; v.f = make_float2(lo, hi); return v.u;
}
__device__ __forceinline__ float2 upk2(ull x) {
    F2U v; v.u = x; return v.f;
}
__device__ __forceinline__ ull fma2(ull a, ull b, ull c) {
    ull d;
    asm("fma.rn.f32x2 %0, %1, %2, %3;" : "=l"(d) : "l"(a), "l"(b), "l"(c));
    return d;
}
__device__ __forceinline__ ull mul2(ull a, ull b) {
    ull d;
    asm("mul.rn.f32x2 %0, %1, %2;" : "=l"(d) : "l"(a), "l"(b));
    return d;
}

// Warp-autonomous persistent encoder (R6 core) with smem-staged coalesced
// output stores. lane = channel-group e; x[e,0..39] packed in registers;
// weights conflict-free [f*30+e]; per-warp stage buffer -> STG.128.
__global__ __launch_bounds__(TH, 4)
void encoder_kernel(const int*    __restrict__ char_ids,
                    const int*    __restrict__ word_ids,
                    const float*  __restrict__ char_emb,
                    const float*  __restrict__ conv_w,
                    const float*  __restrict__ conv_b,
                    const float4* __restrict__ glove4,
                    float*        __restrict__ out,
                    int n_pos)
{
    __shared__ float      emb_s[NCHARS * CHAR_EMB];  // [char][e] (uniform-id reads: conflict-free)
    __shared__ ulonglong2 wsA[900];                  // [f*30+e] = {w0pair, w1pair}
    __shared__ float      wsW2[900];                 // [f*30+e] = w2
    __shared__ float      stg[4][900];               // per-warp output stage

    const int tid  = threadIdx.x;
    const int lane = tid & 31;
    const int wrp  = tid >> 5;

    for (int i = tid; i < NCHARS * CHAR_EMB; i += TH)
        emb_s[i] = char_emb[i];
    for (int oc = tid; oc < 900; oc += TH) {
        const int e = oc / NFILT, f = oc % NFILT;
        const float* wp = conv_w + (size_t)oc * 3;
        ulonglong2 a;
        a.x = pk2(wp[0], wp[0]);
        a.y = pk2(wp[1], wp[1]);
        wsA[f * 30 + e]  = a;
        wsW2[f * 30 + e] = wp[2];
    }
    __syncthreads();

    const int el = (lane < CHAR_EMB) ? lane : CHAR_EMB - 1;  // safe column
    float* stg_w = stg[wrp];

    const int wstride = gridDim.x * (TH / 32);
    int p = blockIdx.x * (TH / 32) + wrp;
    if (p >= n_pos) return;

    int2 c = make_int2(0, 0);
    if (lane < 20) c = reinterpret_cast<const int2*>(char_ids)[(size_t)p * 20 + lane];

    while (true) {
        const int pn = p + wstride;
        int2 cn = make_int2(0, 0);
        if (pn < n_pos && lane < 20)
            cn = reinterpret_cast<const int2*>(char_ids)[(size_t)pn * 20 + lane];

        // glove gather (independent)
        if (lane < 25) {
            const int wid = word_ids[p];
            reinterpret_cast<float4*>(out)[(size_t)p * 250 + 225 + lane] =
                glove4[(size_t)wid * 25 + lane];
        }

        // ---- gather + pack x[e = lane, 0..39] into both conv phases ----
        ull xe[20], xo[19];
        {
#define EV(t) emb_s[__shfl_sync(0xFFFFFFFFu, (((t) & 1) ? c.y : c.x), (t) >> 1) * CHAR_EMB + el]
            float x0 = EV(0);
            float x1 = EV(1);
            xe[0] = pk2(x0, x1);
#pragma unroll
            for (int i = 1; i < 20; i++) {
                float x2 = EV(2 * i);
                float x3 = EV(2 * i + 1);
                xe[i]     = pk2(x2, x3);
                xo[i - 1] = pk2(x1, x2);
                x1 = x3;
            }
#undef EV
        }

        // ---- 30 filters; results staged in smem (no scattered STG) ----
        if (lane < CHAR_EMB) {
#pragma unroll 2
            for (int f = 0; f < NFILT; f++) {
                const ulonglong2 wa = wsA[f * 30 + lane];      // {w0, w1}
                const float      w2 = wsW2[f * 30 + lane];
                const ull w2p = pk2(w2, w2);
                float m0 = -3.402823466e+38f, m1 = m0;
#pragma unroll
                for (int i = 0; i < 19; i++) {
                    ull acc = mul2(w2p, xe[i + 1]);
                    acc = fma2(wa.y, xo[i], acc);
                    acc = fma2(wa.x, xe[i], acc);
                    const float2 y = upk2(acc);
                    m0 = fmaxf(m0, y.x);
                    m1 = fmaxf(m1, y.y);
                }
                stg_w[lane * 30 + f] = fmaxf(m0, m1);
            }
        }
        __syncwarp();

        // ---- coalesced store: 900 floats as float4, bias added here ----
        {
            float* outp = out + (size_t)p * 1000;
#pragma unroll
            for (int it = 0; it < 8; it++) {
                const int j4 = it * 32 + lane;          // float4 index, 225 total
                if (j4 < 225) {
                    const float4 v = reinterpret_cast<const float4*>(stg_w)[j4];
                    const float4 b = __ldg(reinterpret_cast<const float4*>(conv_b) + j4);
                    float4 r;
                    r.x = v.x + b.x; r.y = v.y + b.y;
                    r.z = v.z + b.z; r.w = v.w + b.w;
                    reinterpret_cast<float4*>(outp)[j4] = r;
                }
            }
        }
        __syncwarp();

        if (pn >= n_pos) break;
        p = pn;
        c = cn;
    }
}

extern "C" void kernel_launch(void* const* d_in, const int* in_sizes, int n_in,
                              void* d_out, int out_size)
{
    const int*   char_ids = (const int*)d_in[0];
    const int*   word_ids = (const int*)d_in[1];
    const float* char_emb = (const float*)d_in[2];
    const float* conv_w   = (const float*)d_in[3];
    const float* conv_b   = (const float*)d_in[4];
    const float* glove    = (const float*)d_in[5];
    float*       out      = (float*)d_out;

    const int n_pos = in_sizes[1];   // B*S

    int blocks = 592;                // 4 resident blocks/SM on 148 SMs
    if (blocks * (TH / 32) > n_pos) blocks = (n_pos + TH / 32 - 1) / (TH / 32);
    encoder_kernel<<<blocks, TH>>>(char_ids, word_ids, char_emb, conv_w, conv_b,
                                   (const float4*)glove, out, n_pos);
}